// round 11
// baseline (speedup 1.0000x reference)
#include <cuda_runtime.h>
#include <cuda_bf16.h>
#include <stdint.h>

#define N_NODES 50000
#define N_EDGES 300000
#define DIM 256
#define ALPHA 0.1f

#define SCAN_B 1024
#define N_SCAN_BLK ((N_NODES + SCAN_B - 1) / SCAN_B)   // 49

// ---------------------------------------------------------------------------
// __device__ scratch (allocation-free rule)
// ---------------------------------------------------------------------------
__device__ float g_bufA[(size_t)N_NODES * DIM];
__device__ float g_bufB[(size_t)N_NODES * DIM];
__device__ __nv_bfloat16 g_whi[DIM * DIM];               // W^T hi  [n][k]
__device__ __nv_bfloat16 g_wlo[DIM * DIM];               // W^T lo  [n][k]
__device__ float g_rnorm[N_NODES];
__device__ int   g_src[N_EDGES];
__device__ int   g_dst[N_EDGES];
__device__ int   g_csrc[N_EDGES];
__device__ int   g_rowptr[N_NODES + 1];
__device__ int   g_ideg[N_NODES];
__device__ int   g_cursor[N_NODES];
__device__ int   g_bsum[N_SCAN_BLK];
__device__ int   g_is64;

// ---------------------------------------------------------------------------
// Base-ISA helpers (sm_80+; safe for .target sm_103)
// ---------------------------------------------------------------------------
__device__ __forceinline__ uint32_t smem_u32(const void* p) {
    uint32_t a;
    asm("{ .reg .u64 t; cvta.to.shared.u64 t, %1; cvt.u32.u64 %0, t; }"
        : "=r"(a) : "l"(p));
    return a;
}

__device__ __forceinline__ void ldsm4(uint32_t* r, uint32_t a) {
    asm volatile("ldmatrix.sync.aligned.m8n8.x4.shared.b16 {%0,%1,%2,%3}, [%4];"
        : "=r"(r[0]), "=r"(r[1]), "=r"(r[2]), "=r"(r[3]) : "r"(a));
}

__device__ __forceinline__ void mma16816(float* c, const uint32_t* a,
                                         uint32_t b0, uint32_t b1) {
    asm volatile(
        "mma.sync.aligned.m16n8k16.row.col.f32.bf16.bf16.f32 "
        "{%0,%1,%2,%3}, {%4,%5,%6,%7}, {%8,%9}, {%0,%1,%2,%3};"
        : "+f"(c[0]), "+f"(c[1]), "+f"(c[2]), "+f"(c[3])
        : "r"(a[0]), "r"(a[1]), "r"(a[2]), "r"(a[3]), "r"(b0), "r"(b1));
}

__device__ __forceinline__ void cp16(uint32_t dst, const void* src) {
    asm volatile("cp.async.cg.shared.global [%0], [%1], 16;"
        :: "r"(dst), "l"(src) : "memory");
}
#define CP_COMMIT() asm volatile("cp.async.commit_group;" ::: "memory")
#define CP_WAIT0()  asm volatile("cp.async.wait_group 0;" ::: "memory")

// ---------------------------------------------------------------------------
// Edge dtype detect + decode (int64 vs int32 robust), clamped.
// hist fused into decode (ideg must be zeroed beforehand).
// ---------------------------------------------------------------------------
__global__ void detect_kernel(const int* __restrict__ buf32) {
    if (threadIdx.x == 0 && blockIdx.x == 0) {
        int is64 = 1;
        for (int i = 0; i < 512; i++)
            if (buf32[2 * i + 1] != 0) { is64 = 0; break; }
        g_is64 = is64;
    }
}

__global__ void decode_hist_kernel(const void* __restrict__ buf) {
    int e = blockIdx.x * blockDim.x + threadIdx.x;
    if (e >= N_EDGES) return;
    int s, d;
    if (g_is64) {
        const long long* b = (const long long*)buf;
        s = (int)b[e];  d = (int)b[N_EDGES + e];
    } else {
        const int* b = (const int*)buf;
        s = b[e];       d = b[N_EDGES + e];
    }
    if (s < 0) s = 0; if (s >= N_NODES) s = N_NODES - 1;
    if (d < 0) d = 0; if (d >= N_NODES) d = N_NODES - 1;
    g_src[e] = s;
    g_dst[e] = d;
    atomicAdd(&g_ideg[d], 1);
}

// ---------------------------------------------------------------------------
// CSR build
// ---------------------------------------------------------------------------
__global__ void scan1_kernel() {
    __shared__ int s[SCAN_B];
    int tid = threadIdx.x;
    int i = blockIdx.x * SCAN_B + tid;
    int v = (i < N_NODES) ? g_ideg[i] : 0;
    s[tid] = v;
    __syncthreads();
    for (int off = 1; off < SCAN_B; off <<= 1) {
        int t = (tid >= off) ? s[tid - off] : 0;
        __syncthreads();
        s[tid] += t;
        __syncthreads();
    }
    if (i < N_NODES) g_rowptr[i] = s[tid] - v;
    if (tid == SCAN_B - 1) g_bsum[blockIdx.x] = s[tid];
}

__global__ void scan2_kernel() {
    __shared__ int s[N_SCAN_BLK];
    int tid = threadIdx.x;
    if (tid < N_SCAN_BLK) s[tid] = g_bsum[tid];
    __syncthreads();
    if (tid == 0) {
        int acc = 0;
        for (int i = 0; i < N_SCAN_BLK; i++) { int t = s[i]; s[i] = acc; acc += t; }
    }
    __syncthreads();
    if (tid < N_SCAN_BLK) g_bsum[tid] = s[tid];
}

// scan3 + rnorm fused
__global__ void scan3_kernel() {
    int i = blockIdx.x * SCAN_B + threadIdx.x;
    if (i < N_NODES) {
        g_rowptr[i] += g_bsum[blockIdx.x];
        g_rnorm[i] = (1.0f - ALPHA) / fmaxf((float)g_ideg[i], 1.0f);
    }
    if (i == 0) g_rowptr[N_NODES] = N_EDGES;
}

__global__ void fill_kernel() {
    int e = blockIdx.x * blockDim.x + threadIdx.x;
    if (e >= N_EDGES) return;
    int d = g_dst[e];
    int p = atomicAdd(&g_cursor[d], 1);
    g_csrc[g_rowptr[d] + p] = g_src[e];
}

// ---------------------------------------------------------------------------
// W split + transpose: g_whi/g_wlo[n][k] = bf16 hi/lo of W[k][n]
// ---------------------------------------------------------------------------
__global__ void wsplit_kernel(const float* __restrict__ W) {
    int idx = blockIdx.x * blockDim.x + threadIdx.x;
    if (idx >= DIM * DIM) return;
    int k = idx >> 8, n = idx & 255;
    float w = W[k * DIM + n];
    __nv_bfloat16 hi = __float2bfloat16_rn(w);
    float rem = w - __bfloat162float(hi);
    g_whi[n * DIM + k] = hi;
    g_wlo[n * DIM + k] = __float2bfloat16_rn(rem);
}

// ---------------------------------------------------------------------------
// FUSED gather + split-bf16 GEMM:  out = relu( (a*x0 + rn*sum_nbr x) @ W )
// CTA: 128 rows (m-block) x FULL N=256, 256 threads, 8 warps (4M x 2N),
// warp tile 32x128.  K in 4 chunks of 64.
// A tile is PRODUCED in-kernel (CSR gather fp32 -> mix -> bf16 hi/lo split
// -> swizzled STS).  B (W^T hi/lo) streamed via cp.async double buffer.
// Stage: Ahi 16K @0 | Alo 16K @16K | Bhi 32K @32K | Blo 32K @64K  (96KB);
// 2 stages = 192KB dynamic smem (1 CTA/SM).
// Terms: Ah@Wh + Ah@Wl + Al@Wh  (fp32-class accuracy).
// ---------------------------------------------------------------------------
#define SWZOFF(row, c) ((unsigned)((row) * 128 + (((c) ^ ((row) & 7)) << 4)))
#define STAGE_BYTES 98304
#define A_LO_OFF 16384
#define B_HI_OFF 32768
#define B_LO_OFF 65536

__device__ __forceinline__ void add4(float4& a, const float4 b) {
    a.x += b.x; a.y += b.y; a.z += b.z; a.w += b.w;
}

// Produce A tile chunk: thread t handles row r=t>>1, k-half kh=(t&1)*32.
__device__ __forceinline__ void produce_A(char* dsm, uint32_t stage_off,
                                          const float* __restrict__ xin,
                                          const float* __restrict__ x0,
                                          int row, int valid, int s, int e,
                                          float rn, int k0, int tid) {
    const int r = tid >> 1;
    const int kh = (tid & 1) * 32;            // float offset inside chunk
    const int jb = (tid & 1) * 4;             // 16B-chunk base index

    float4 f[8] = {};
    if (valid) {
        const int koff = k0 + kh;
        int i = s;
        for (; i + 1 < e; i += 2) {
            const float4* p0 = (const float4*)(xin + (size_t)g_csrc[i] * DIM + koff);
            const float4* p1 = (const float4*)(xin + (size_t)g_csrc[i + 1] * DIM + koff);
            #pragma unroll
            for (int j = 0; j < 8; j++) { add4(f[j], p0[j]); add4(f[j], p1[j]); }
        }
        if (i < e) {
            const float4* p0 = (const float4*)(xin + (size_t)g_csrc[i] * DIM + koff);
            #pragma unroll
            for (int j = 0; j < 8; j++) add4(f[j], p0[j]);
        }
        const float4* q = (const float4*)(x0 + (size_t)row * DIM + koff);
        #pragma unroll
        for (int j = 0; j < 8; j++) {
            float4 qq = q[j];
            f[j].x = ALPHA * qq.x + rn * f[j].x;
            f[j].y = ALPHA * qq.y + rn * f[j].y;
            f[j].z = ALPHA * qq.z + rn * f[j].z;
            f[j].w = ALPHA * qq.w + rn * f[j].w;
        }
    }
    // split + pack: per 16B chunk = 8 floats -> 4 bf16x2 hi + 4 bf16x2 lo
    #pragma unroll
    for (int j4 = 0; j4 < 4; j4++) {
        const float hv[8] = { f[j4*2].x, f[j4*2].y, f[j4*2].z, f[j4*2].w,
                              f[j4*2+1].x, f[j4*2+1].y, f[j4*2+1].z, f[j4*2+1].w };
        uint32_t hi[4], lo[4];
        #pragma unroll
        for (int p = 0; p < 4; p++) {
            float v0 = hv[p*2], v1 = hv[p*2+1];
            __nv_bfloat16 b0 = __float2bfloat16_rn(v0);
            __nv_bfloat16 b1 = __float2bfloat16_rn(v1);
            __nv_bfloat16 c0 = __float2bfloat16_rn(v0 - __bfloat162float(b0));
            __nv_bfloat16 c1 = __float2bfloat16_rn(v1 - __bfloat162float(b1));
            __nv_bfloat162 ph = __halves2bfloat162(b0, b1);
            __nv_bfloat162 pl = __halves2bfloat162(c0, c1);
            hi[p] = *(uint32_t*)&ph;
            lo[p] = *(uint32_t*)&pl;
        }
        unsigned off = SWZOFF(r, jb + j4);
        *(uint4*)(dsm + stage_off + off)            = make_uint4(hi[0],hi[1],hi[2],hi[3]);
        *(uint4*)(dsm + stage_off + A_LO_OFF + off) = make_uint4(lo[0],lo[1],lo[2],lo[3]);
    }
}

__device__ __forceinline__ void load_B(uint32_t ustage, int k0, int tid) {
    #pragma unroll
    for (int t = 0; t < 8; t++) {
        int idx = tid + t * 256;
        int r = idx >> 3, j = idx & 7;     // r: 0..255 n-rows, j: 16B chunk
        unsigned off = SWZOFF(r, j);
        cp16(ustage + B_HI_OFF + off, g_whi + (size_t)r * DIM + k0 + j * 8);
        cp16(ustage + B_LO_OFF + off, g_wlo + (size_t)r * DIM + k0 + j * 8);
    }
}

__global__ void __launch_bounds__(256) fused_kernel(
        const float* __restrict__ xin, const float* __restrict__ x0,
        float* __restrict__ out) {
    extern __shared__ __align__(16) char dsm[];

    const int tid = threadIdx.x;
    const int wid = tid >> 5, lane = tid & 31;
    const int m0 = blockIdx.x * 128;
    const int wm = (wid >> 1) * 32;      // 4 warps in M
    const int wn = (wid & 1) * 128;      // 2 warps in N

    const uint32_t usm = smem_u32(dsm);

    // Per-thread produce metadata (row r = tid>>1), cached across chunks
    const int prow = m0 + (tid >> 1);
    const int pvalid = (prow < N_NODES);
    const int ps = pvalid ? g_rowptr[prow] : 0;
    const int pe = pvalid ? g_rowptr[prow + 1] : 0;
    const float prn = pvalid ? g_rnorm[prow] : 0.0f;

    float acc[2][16][4] = {};

    // Prologue: chunk 0
    produce_A(dsm, 0, xin, x0, prow, pvalid, ps, pe, prn, 0, tid);
    load_B(usm, 0, tid);
    CP_COMMIT();

    for (int ch = 0; ch < 4; ch++) {
        const uint32_t stage_off = (ch & 1) * STAGE_BYTES;
        const uint32_t ub = usm + stage_off;
        CP_WAIT0();
        __syncthreads();
        if (ch < 3) {
            const uint32_t nso = ((ch + 1) & 1) * STAGE_BYTES;
            produce_A(dsm, nso, xin, x0, prow, pvalid, ps, pe, prn,
                      (ch + 1) * 64, tid);
            load_B(usm + nso, (ch + 1) * 64, tid);
            CP_COMMIT();
        }

        const uint32_t uAhi = ub, uAlo = ub + A_LO_OFF;
        const uint32_t uBhi = ub + B_HI_OFF, uBlo = ub + B_LO_OFF;

        #pragma unroll
        for (int kk = 0; kk < 4; kk++) {
            uint32_t ah[2][4], al[2][4];
            #pragma unroll
            for (int mi = 0; mi < 2; mi++) {
                int row = wm + mi * 16 + (lane & 15);
                int c = kk * 2 + (lane >> 4);
                unsigned off = SWZOFF(row, c);
                ldsm4(ah[mi], uAhi + off);
                ldsm4(al[mi], uAlo + off);
            }
            #pragma unroll
            for (int q = 0; q < 8; q++) {
                int n = wn + q * 16 + ((lane >> 4) << 3) + (lane & 7);
                int c = kk * 2 + ((lane >> 3) & 1);
                unsigned off = SWZOFF(n, c);
                uint32_t bh[4], bl[4];
                ldsm4(bh, uBhi + off);
                ldsm4(bl, uBlo + off);
                #pragma unroll
                for (int par = 0; par < 2; par++) {
                    int nj = 2 * q + par;
                    int hb = par * 2;
                    #pragma unroll
                    for (int mi = 0; mi < 2; mi++) {
                        mma16816(acc[mi][nj], ah[mi], bh[hb], bh[hb + 1]);
                        mma16816(acc[mi][nj], ah[mi], bl[hb], bl[hb + 1]);
                        mma16816(acc[mi][nj], al[mi], bh[hb], bh[hb + 1]);
                    }
                }
            }
        }
        __syncthreads();
    }

    // Epilogue: ReLU + guarded float2 stores
    #pragma unroll
    for (int mi = 0; mi < 2; mi++) {
        #pragma unroll
        for (int nj = 0; nj < 16; nj++) {
            int r = m0 + wm + mi * 16 + (lane >> 2);
            int cbase = wn + nj * 8 + (lane & 3) * 2;
            float2 v0, v1;
            v0.x = fmaxf(acc[mi][nj][0], 0.f);
            v0.y = fmaxf(acc[mi][nj][1], 0.f);
            v1.x = fmaxf(acc[mi][nj][2], 0.f);
            v1.y = fmaxf(acc[mi][nj][3], 0.f);
            if (r < N_NODES)
                *(float2*)(out + (size_t)r * DIM + cbase) = v0;
            if (r + 8 < N_NODES)
                *(float2*)(out + (size_t)(r + 8) * DIM + cbase) = v1;
        }
    }
}

// ---------------------------------------------------------------------------
// Launch (all graph-capturable)
// ---------------------------------------------------------------------------
extern "C" void kernel_launch(void* const* d_in, const int* in_sizes, int n_in,
                              void* d_out, int out_size) {
    const float* x0   = (const float*)d_in[0];
    const void*  edge = d_in[1];
    const float* W    = (const float*)d_in[2];
    float*       out  = (float*)d_out;

    void *ideg_p, *cursor_p, *bufA_p, *bufB_p;
    cudaGetSymbolAddress(&ideg_p,   g_ideg);
    cudaGetSymbolAddress(&cursor_p, g_cursor);
    cudaGetSymbolAddress(&bufA_p,   g_bufA);
    cudaGetSymbolAddress(&bufB_p,   g_bufB);

    cudaFuncSetAttribute(fused_kernel,
                         cudaFuncAttributeMaxDynamicSharedMemorySize,
                         2 * STAGE_BYTES);
    cudaFuncSetAttribute(fused_kernel,
                         cudaFuncAttributePreferredSharedMemoryCarveout,
                         cudaSharedmemCarveoutMaxShared);

    const int EB = (N_EDGES + 255) / 256;

    // Prologue (layer-invariant): decode+hist, CSR scan, fill, rnorm, wsplit
    detect_kernel<<<1, 32>>>((const int*)edge);
    cudaMemsetAsync(ideg_p,   0, N_NODES * sizeof(int), 0);
    cudaMemsetAsync(cursor_p, 0, N_NODES * sizeof(int), 0);
    decode_hist_kernel<<<EB, 256>>>(edge);
    scan1_kernel<<<N_SCAN_BLK, SCAN_B>>>();
    scan2_kernel<<<1, 64>>>();
    scan3_kernel<<<N_SCAN_BLK, SCAN_B>>>();
    fill_kernel<<<EB, 256>>>();
    wsplit_kernel<<<(DIM * DIM + 255) / 256, 256>>>(W);

    float* layer_out[5] = {(float*)bufA_p, (float*)bufB_p,
                           (float*)bufA_p, (float*)bufB_p, out};

    const int ggrid = (N_NODES + 127) / 128;   // 391

    const float* xin = x0;
    for (int l = 0; l < 5; l++) {
        fused_kernel<<<ggrid, 256, 2 * STAGE_BYTES>>>(xin, x0, layer_out[l]);
        xin = layer_out[l];
    }
}